// round 12
// baseline (speedup 1.0000x reference)
#include <cuda_runtime.h>

// EnhancedLIFNeuron on GB300: Conv1d(1,1,5,'same') + spatial attention + LIF scan.
// B=128, T=128, F=2048. Each thread owns FOUR adjacent feature chains as TWO
// packed f32x2 streams. No SMEM. Phase 1 streams x (default/evict_normal, keeps
// x in L2); phase 2 re-reads with ld.global.cs through an 8-deep register
// prefetch ring; all stores st.global.cs. blockDim=64, grid=1024 for wave balance.

#define Tn 128
#define Fn 2048
#define Bn 128
#define BD 64

typedef unsigned long long u64;

__device__ __forceinline__ u64 pk(float lo, float hi) {
    u64 r; asm("mov.b64 %0,{%1,%2};" : "=l"(r) : "f"(lo), "f"(hi)); return r;
}
__device__ __forceinline__ void upk(u64 v, float& lo, float& hi) {
    asm("mov.b64 {%0,%1},%2;" : "=f"(lo), "=f"(hi) : "l"(v));
}
__device__ __forceinline__ u64 f2fma(u64 a, u64 b, u64 c) {
    u64 d; asm("fma.rn.f32x2 %0,%1,%2,%3;" : "=l"(d) : "l"(a), "l"(b), "l"(c)); return d;
}
__device__ __forceinline__ u64 f2mul(u64 a, u64 b) {
    u64 d; asm("mul.rn.f32x2 %0,%1,%2;" : "=l"(d) : "l"(a), "l"(b)); return d;
}
__device__ __forceinline__ u64 f2add(u64 a, u64 b) {
    u64 d; asm("add.rn.f32x2 %0,%1,%2;" : "=l"(d) : "l"(a), "l"(b)); return d;
}
__device__ __forceinline__ float frcp_ap(float a) {
    float r; asm("rcp.approx.ftz.f32 %0,%1;" : "=f"(r) : "f"(a)); return r;
}
__device__ __forceinline__ float fsqrt_ap(float a) {
    float r; asm("sqrt.approx.ftz.f32 %0,%1;" : "=f"(r) : "f"(a)); return r;
}
// phase-2 load: streaming (evict-first)
__device__ __forceinline__ float4 ld_once4(const float4* p) {
    float4 v;
    asm("ld.global.cs.v4.f32 {%0,%1,%2,%3},[%4];"
        : "=f"(v.x), "=f"(v.y), "=f"(v.z), "=f"(v.w) : "l"(p));
    return v;
}
// streaming store (evict-first)
__device__ __forceinline__ void st_stream2(ulonglong2* p, u64 a, u64 b) {
    asm volatile("st.global.cs.v2.u64 [%0],{%1,%2};" :: "l"(p), "l"(a), "l"(b) : "memory");
}

#define SMASK 0x8000000080000000ull

__global__ void lif_kernel(const float* __restrict__ x,
                           const float* __restrict__ thr0p,
                           const float* __restrict__ convw,
                           const float* __restrict__ convb,
                           const float* __restrict__ sap,
                           float* __restrict__ out)
{
    const int cid = blockIdx.x * BD + threadIdx.x;    // quad-chain id
    const int b   = cid >> 9;                         // Fn/4 = 512 quads per batch
    const int fq  = cid & 511;
    const float4* __restrict__ px4 =
        reinterpret_cast<const float4*>(x + (size_t)b * Tn * Fn) + fq;  // + t*512

    // ---- scalars ----
    const float thr0 = __ldg(thr0p);
    const float w0 = __ldg(convw + 0), w1 = __ldg(convw + 1), w2 = __ldg(convw + 2),
                w3 = __ldg(convw + 3), w4 = __ldg(convw + 4);
    const float cb = __ldg(convb);
    const float sa = __ldg(sap);

    // ---- phase 1: packed sums over t (default loads keep x in L2) ----
    u64 aA0 = 0, aA1 = 0, aB0 = 0, aB1 = 0;
    float4 r0v, r1v, r2v, r126, r127;
    #pragma unroll 8
    for (int t = 0; t < Tn; t += 2) {
        float4 v0 = __ldg(px4 + (t + 0) * 512);
        float4 v1 = __ldg(px4 + (t + 1) * 512);
        if (t == 0)   { r0v = v0; r1v = v1; }
        if (t == 2)   { r2v = v0; }
        if (t == 126) { r126 = v0; r127 = v1; }
        aA0 = f2add(aA0, pk(v0.x, v0.y));  aB0 = f2add(aB0, pk(v0.z, v0.w));
        aA1 = f2add(aA1, pk(v1.x, v1.y));  aB1 = f2add(aB1, pk(v1.z, v1.w));
    }
    float sA0, sA1, sB0, sB1;
    upk(f2add(aA0, aA1), sA0, sA1);
    upk(f2add(aB0, aB1), sB0, sB1);

    // closed-form mean of conv output, then attention scale per lane
    const float W   = ((w0 + w1) + w2) + (w3 + w4);
    const float c34 = w3 + w4, c01 = w0 + w1;
#define MEANL(S, X0, X1, X126, X127) \
    ((W * (S) - c34 * (X0) - w4 * (X1) - w0 * (X126) - c01 * (X127)) * (1.0f/Tn) + cb)
    float m0 = MEANL(sA0, r0v.x, r1v.x, r126.x, r127.x);
    float m1 = MEANL(sA1, r0v.y, r1v.y, r126.y, r127.y);
    float m2 = MEANL(sB0, r0v.z, r1v.z, r126.z, r127.z);
    float m3 = MEANL(sB1, r0v.w, r1v.w, r126.w, r127.w);
#undef MEANL
    float sc0 = 1.0f + 0.5f / (1.0f + __expf(-sa * m0));   // GAMMA = 0.5
    float sc1 = 1.0f + 0.5f / (1.0f + __expf(-sa * m1));
    float sc2 = 1.0f + 0.5f / (1.0f + __expf(-sa * m2));
    float sc3 = 1.0f + 0.5f / (1.0f + __expf(-sa * m3));

    // scaled conv weights, packed per pair
    const u64 VA0 = pk(w0*sc0, w0*sc1), VB0 = pk(w0*sc2, w0*sc3);
    const u64 VA1 = pk(w1*sc0, w1*sc1), VB1 = pk(w1*sc2, w1*sc3);
    const u64 VA2 = pk(w2*sc0, w2*sc1), VB2 = pk(w2*sc2, w2*sc3);
    const u64 VA3 = pk(w3*sc0, w3*sc1), VB3 = pk(w3*sc2, w3*sc3);
    const u64 VA4 = pk(w4*sc0, w4*sc1), VB4 = pk(w4*sc2, w4*sc3);
    const u64 VAb = pk(cb*sc0, cb*sc1), VBb = pk(cb*sc2, cb*sc3);

    // ---- packed constants ----
    const float PI = 3.14159265358979323846f;
    const float INVPI = 1.0f / PI;
    const u64 DEC  = pk(0.9f, 0.9f);                  // DECAY == ALPHA
    const u64 CARG = pk(PI*0.5f, PI*0.5f);
    const u64 QRT  = pk(0.25f, 0.25f);
    const u64 ONE  = pk(1.0f, 1.0f);
    const u64 CAVG = pk(0.1f/3.0f, 0.1f/3.0f);
    const u64 CT0  = pk(0.1f*thr0, 0.1f*thr0);
    const u64 P0 = pk( 0.9998660f*INVPI,  0.9998660f*INVPI);
    const u64 P1 = pk(-0.3302995f*INVPI, -0.3302995f*INVPI);
    const u64 P2 = pk( 0.1801410f*INVPI,  0.1801410f*INVPI);
    const u64 P3 = pk(-0.0851330f*INVPI, -0.0851330f*INVPI);
    const u64 P4 = pk( 0.0208351f*INVPI,  0.0208351f*INVPI);

    // ---- LIF state, two packed pairs (A = f,f+1 ; B = f+2,f+3) ----
    u64 memA = 0, thrA = pk(thr0, thr0), h2A = 0, h12A = 0;
    u64 memB = 0, thrB = pk(thr0, thr0), h2B = 0, h12B = 0;
    u64 am2 = 0, am1 = 0, ac = pk(r0v.x, r0v.y), ap1 = pk(r1v.x, r1v.y), ap2 = pk(r2v.x, r2v.y);
    u64 bm2 = 0, bm1 = 0, bc = pk(r0v.z, r0v.w), bp1 = pk(r1v.z, r1v.w), bp2 = pk(r2v.z, r2v.w);

    // 8-deep prefetch ring: q = x[g+3..g+6], r = x[g+7..g+10]
    float4 q0 = ld_once4(px4 + 3*512);
    float4 q1 = ld_once4(px4 + 4*512);
    float4 q2 = ld_once4(px4 + 5*512);
    float4 q3 = ld_once4(px4 + 6*512);
    float4 r0 = ld_once4(px4 + 7*512);
    float4 r1 = ld_once4(px4 + 8*512);
    float4 r2 = ld_once4(px4 + 9*512);
    float4 r3 = ld_once4(px4 + 10*512);
    const float4 z4 = make_float4(0.f, 0.f, 0.f, 0.f);

    ulonglong2* __restrict__ opp =
        reinterpret_cast<ulonglong2*>(out + (size_t)b * Tn * Fn) + fq;  // + t*512

#define PAIRSTEP(mem, thr, h2, h12, xm2, xm1, xc, xp1, xp2, V0,V1,V2,V3,V4,Vb, XNEW, SPK) \
    do {                                                                     \
        u64 cv = f2fma(V0, xm2, f2fma(V1, xm1, f2fma(V2, xc,                 \
                 f2fma(V3, xp1, f2fma(V4, xp2, Vb)))));                      \
        mem = f2fma(DEC, mem, cv);                                           \
        u64 z  = f2mul(f2add(mem, thr ^ SMASK), CARG);                       \
        u64 o  = f2fma(z, z, ONE);                                           \
        float olo, ohi; upk(o, olo, ohi);                                    \
        float rlo = frcp_ap(1.0f + fsqrt_ap(olo));                           \
        float rhi = frcp_ap(1.0f + fsqrt_ap(ohi));                           \
        u64 tq = f2mul(z, pk(rlo, rhi));                                     \
        u64 tt = f2mul(tq, tq);                                              \
        u64 t4 = f2mul(tt, tt);                                              \
        u64 pa = f2fma(P1, tt, P0);                                          \
        u64 pb = f2fma(P3, tt, P2);                                          \
        u64 pc = f2fma(P4, t4, pb);                                          \
        u64 p  = f2fma(pc, t4, pa);                                          \
        u64 spike = f2fma(tq, p, QRT);                                       \
        u64 s3 = f2add(h12, spike);                                          \
        thr = f2fma(DEC, thr, f2fma(CAVG, s3, CT0));                         \
        mem = f2fma(spike ^ SMASK, thr, mem);                                \
        h12 = f2add(h2, spike); h2 = spike;                                  \
        xm2 = xm1; xm1 = xc; xc = xp1; xp1 = xp2; xp2 = (XNEW);              \
        SPK = spike;                                                         \
    } while (0)

#define QSTEP(Q) do {                                                        \
        u64 spA, spB;                                                        \
        PAIRSTEP(memA, thrA, h2A, h12A, am2, am1, ac, ap1, ap2,              \
                 VA0,VA1,VA2,VA3,VA4,VAb, pk((Q).x,(Q).y), spA);             \
        PAIRSTEP(memB, thrB, h2B, h12B, bm2, bm1, bc, bp1, bp2,              \
                 VB0,VB1,VB2,VB3,VB4,VBb, pk((Q).z,(Q).w), spB);             \
        st_stream2(opp, spA, spB); opp += 512;                               \
    } while (0)

    // main loop: groups g = 0..112 (29 iters), unconditional prefetch of
    // t = g+11..g+14 (max t = 126), consumed 8 steps later
    const float4* pf = px4 + 11 * 512;
    #pragma unroll 1
    for (int g = 0; g <= 112; g += 4) {
        float4 n0 = ld_once4(pf + 0*512);
        float4 n1 = ld_once4(pf + 1*512);
        float4 n2 = ld_once4(pf + 2*512);
        float4 n3 = ld_once4(pf + 3*512);
        pf += 4*512;

        QSTEP(q0); QSTEP(q1); QSTEP(q2); QSTEP(q3);

        q0 = r0; q1 = r1; q2 = r2; q3 = r3;
        r0 = n0; r1 = n1; r2 = n2; r3 = n3;
    }
    // g = 116: consume q = x[119..122]; refill r = {x127, 0, 0, 0}
    {
        float4 n0 = ld_once4(px4 + 127*512);
        QSTEP(q0); QSTEP(q1); QSTEP(q2); QSTEP(q3);
        q0 = r0; q1 = r1; q2 = r2; q3 = r3;
        r0 = n0; r1 = z4; r2 = z4; r3 = z4;
    }
    // g = 120: consume q = x[123..126]
    QSTEP(q0); QSTEP(q1); QSTEP(q2); QSTEP(q3);
    q0 = r0; q1 = r1; q2 = r2; q3 = r3;
    // g = 124: consume q = {x127, 0, 0, 0}
    QSTEP(q0); QSTEP(q1); QSTEP(q2); QSTEP(q3);
#undef QSTEP
#undef PAIRSTEP

    // final membrane potential: out[B*T*F + b*F + f]
    st_stream2(reinterpret_cast<ulonglong2*>(out + (size_t)Bn * Tn * Fn + (size_t)b * Fn) + fq,
               memA, memB);
}

extern "C" void kernel_launch(void* const* d_in, const int* in_sizes, int n_in,
                              void* d_out, int out_size)
{
    (void)in_sizes; (void)n_in; (void)out_size;
    const float* x    = (const float*)d_in[0];
    const float* thr0 = (const float*)d_in[1];
    const float* cw   = (const float*)d_in[2];
    const float* cbp  = (const float*)d_in[3];
    const float* sa   = (const float*)d_in[4];
    float* out = (float*)d_out;

    lif_kernel<<<(Bn * Fn) / (BD * 4), BD>>>(x, thr0, cw, cbp, sa, out);
}

// round 13
// speedup vs baseline: 1.3519x; 1.3519x over previous
#include <cuda_runtime.h>

// EnhancedLIFNeuron on GB300: Conv1d(1,1,5,'same') + spatial attention + LIF scan.
// B=128, T=128, F=2048. Each thread owns ONE packed f32x2 pair (2 adjacent
// feature chains). No SMEM. Phase 1 streams x (default/evict_normal, keeps x
// in L2); phase 2 re-reads with ld.global.cs through a 4-deep register ring;
// all stores st.global.cs. grid=1024, block=128 -> ~7 blocks/SM, balanced wave.

#define Tn 128
#define Fn 2048
#define Bn 128
#define BD 128

typedef unsigned long long u64;

__device__ __forceinline__ u64 pk(float lo, float hi) {
    u64 r; asm("mov.b64 %0,{%1,%2};" : "=l"(r) : "f"(lo), "f"(hi)); return r;
}
__device__ __forceinline__ void upk(u64 v, float& lo, float& hi) {
    asm("mov.b64 {%0,%1},%2;" : "=f"(lo), "=f"(hi) : "l"(v));
}
__device__ __forceinline__ u64 f2fma(u64 a, u64 b, u64 c) {
    u64 d; asm("fma.rn.f32x2 %0,%1,%2,%3;" : "=l"(d) : "l"(a), "l"(b), "l"(c)); return d;
}
__device__ __forceinline__ u64 f2mul(u64 a, u64 b) {
    u64 d; asm("mul.rn.f32x2 %0,%1,%2;" : "=l"(d) : "l"(a), "l"(b)); return d;
}
__device__ __forceinline__ u64 f2add(u64 a, u64 b) {
    u64 d; asm("add.rn.f32x2 %0,%1,%2;" : "=l"(d) : "l"(a), "l"(b)); return d;
}
__device__ __forceinline__ float frcp_ap(float a) {
    float r; asm("rcp.approx.ftz.f32 %0,%1;" : "=f"(r) : "f"(a)); return r;
}
__device__ __forceinline__ float fsqrt_ap(float a) {
    float r; asm("sqrt.approx.ftz.f32 %0,%1;" : "=f"(r) : "f"(a)); return r;
}
// phase-2 load: streaming (evict-first)
__device__ __forceinline__ float2 ld_once2(const float2* p) {
    float2 v;
    asm("ld.global.cs.v2.f32 {%0,%1},[%2];" : "=f"(v.x), "=f"(v.y) : "l"(p));
    return v;
}
// streaming store (evict-first)
__device__ __forceinline__ void st_stream1(u64* p, u64 a) {
    asm volatile("st.global.cs.b64 [%0],%1;" :: "l"(p), "l"(a) : "memory");
}

#define SMASK 0x8000000080000000ull

__global__ __launch_bounds__(BD, 6)
void lif_kernel(const float* __restrict__ x,
                const float* __restrict__ thr0p,
                const float* __restrict__ convw,
                const float* __restrict__ convb,
                const float* __restrict__ sap,
                float* __restrict__ out)
{
    const int cid = blockIdx.x * BD + threadIdx.x;    // pair-chain id
    const int b   = cid >> 10;                        // Fn/2 = 1024 pairs per batch
    const int fp  = cid & 1023;                       // pair index; f = 2*fp
    const float2* __restrict__ px2 =
        reinterpret_cast<const float2*>(x + (size_t)b * Tn * Fn) + fp;  // + t*1024

    // ---- scalars ----
    const float thr0 = __ldg(thr0p);
    const float w0 = __ldg(convw + 0), w1 = __ldg(convw + 1), w2 = __ldg(convw + 2),
                w3 = __ldg(convw + 3), w4 = __ldg(convw + 4);
    const float cb = __ldg(convb);
    const float sa = __ldg(sap);

    // ---- phase 1: packed sum over t (default loads keep x in L2) ----
    u64 a0 = 0, a1 = 0, a2 = 0, a3 = 0;
    float2 r0v, r1v, r2v, r126, r127;
    #pragma unroll 4
    for (int t = 0; t < Tn; t += 4) {
        float2 v0 = __ldg(px2 + (t + 0) * 1024);
        float2 v1 = __ldg(px2 + (t + 1) * 1024);
        float2 v2 = __ldg(px2 + (t + 2) * 1024);
        float2 v3 = __ldg(px2 + (t + 3) * 1024);
        if (t == 0)   { r0v = v0; r1v = v1; r2v = v2; }
        if (t == 124) { r126 = v2; r127 = v3; }
        a0 = f2add(a0, pk(v0.x, v0.y));
        a1 = f2add(a1, pk(v1.x, v1.y));
        a2 = f2add(a2, pk(v2.x, v2.y));
        a3 = f2add(a3, pk(v3.x, v3.y));
    }
    float s0, s1;
    upk(f2add(f2add(a0, a1), f2add(a2, a3)), s0, s1);

    // closed-form mean of conv output, then attention scale per lane
    const float W   = ((w0 + w1) + w2) + (w3 + w4);
    const float c34 = w3 + w4, c01 = w0 + w1;
#define MEANL(S, X0, X1, X126, X127) \
    ((W * (S) - c34 * (X0) - w4 * (X1) - w0 * (X126) - c01 * (X127)) * (1.0f/Tn) + cb)
    float m0 = MEANL(s0, r0v.x, r1v.x, r126.x, r127.x);
    float m1 = MEANL(s1, r0v.y, r1v.y, r126.y, r127.y);
#undef MEANL
    float sc0 = 1.0f + 0.5f / (1.0f + __expf(-sa * m0));   // GAMMA = 0.5
    float sc1 = 1.0f + 0.5f / (1.0f + __expf(-sa * m1));

    // scaled conv weights, packed
    const u64 V0 = pk(w0*sc0, w0*sc1);
    const u64 V1 = pk(w1*sc0, w1*sc1);
    const u64 V2 = pk(w2*sc0, w2*sc1);
    const u64 V3 = pk(w3*sc0, w3*sc1);
    const u64 V4 = pk(w4*sc0, w4*sc1);
    const u64 Vb = pk(cb*sc0, cb*sc1);

    // ---- packed constants ----
    const float PI = 3.14159265358979323846f;
    const float INVPI = 1.0f / PI;
    const u64 DEC  = pk(0.9f, 0.9f);                  // DECAY == ALPHA
    const u64 CARG = pk(PI*0.5f, PI*0.5f);
    const u64 QRT  = pk(0.25f, 0.25f);
    const u64 ONE  = pk(1.0f, 1.0f);
    const u64 CAVG = pk(0.1f/3.0f, 0.1f/3.0f);
    const u64 CT0  = pk(0.1f*thr0, 0.1f*thr0);
    const u64 P0 = pk( 0.9998660f*INVPI,  0.9998660f*INVPI);
    const u64 P1 = pk(-0.3302995f*INVPI, -0.3302995f*INVPI);
    const u64 P2 = pk( 0.1801410f*INVPI,  0.1801410f*INVPI);
    const u64 P3 = pk(-0.0851330f*INVPI, -0.0851330f*INVPI);
    const u64 P4 = pk( 0.0208351f*INVPI,  0.0208351f*INVPI);

    // ---- LIF state, one packed pair ----
    u64 mem = 0, thr = pk(thr0, thr0), h2 = 0, h12 = 0;
    u64 xm2 = 0, xm1 = 0;
    u64 xc  = pk(r0v.x, r0v.y);
    u64 xp1 = pk(r1v.x, r1v.y);
    u64 xp2 = pk(r2v.x, r2v.y);

    // 4-deep prefetch ring: q = x[3..6]
    float2 q0 = ld_once2(px2 + 3*1024);
    float2 q1 = ld_once2(px2 + 4*1024);
    float2 q2 = ld_once2(px2 + 5*1024);
    float2 q3 = ld_once2(px2 + 6*1024);
    const float2 z2 = make_float2(0.f, 0.f);

    u64* __restrict__ opp =
        reinterpret_cast<u64*>(out + (size_t)b * Tn * Fn) + fp;  // + t*1024

#define QSTEP(Q) do {                                                        \
        u64 cv = f2fma(V0, xm2, f2fma(V1, xm1, f2fma(V2, xc,                 \
                 f2fma(V3, xp1, f2fma(V4, xp2, Vb)))));                      \
        mem = f2fma(DEC, mem, cv);                                           \
        u64 z  = f2mul(f2add(mem, thr ^ SMASK), CARG);                       \
        u64 o  = f2fma(z, z, ONE);                                           \
        float olo, ohi; upk(o, olo, ohi);                                    \
        float rlo = frcp_ap(1.0f + fsqrt_ap(olo));                           \
        float rhi = frcp_ap(1.0f + fsqrt_ap(ohi));                           \
        u64 tq = f2mul(z, pk(rlo, rhi));                                     \
        u64 tt = f2mul(tq, tq);                                              \
        u64 t4 = f2mul(tt, tt);                                              \
        u64 pa = f2fma(P1, tt, P0);                                          \
        u64 pb = f2fma(P3, tt, P2);                                          \
        u64 p  = f2fma(f2fma(P4, t4, pb), t4, pa);                           \
        u64 spike = f2fma(tq, p, QRT);                                       \
        u64 s3 = f2add(h12, spike);                                          \
        thr = f2fma(DEC, thr, f2fma(CAVG, s3, CT0));                         \
        mem = f2fma(spike ^ SMASK, thr, mem);                                \
        h12 = f2add(h2, spike); h2 = spike;                                  \
        xm2 = xm1; xm1 = xc; xc = xp1; xp1 = xp2; xp2 = pk((Q).x, (Q).y);    \
        st_stream1(opp, spike); opp += 1024;                                 \
    } while (0)

    for (int g = 0; g < Tn; g += 4) {
        int tb = g + 7;   // prefetch 4-7 steps ahead
        float2 n0 = (tb + 0 < Tn) ? ld_once2(px2 + (tb + 0) * 1024) : z2;
        float2 n1 = (tb + 1 < Tn) ? ld_once2(px2 + (tb + 1) * 1024) : z2;
        float2 n2 = (tb + 2 < Tn) ? ld_once2(px2 + (tb + 2) * 1024) : z2;
        float2 n3 = (tb + 3 < Tn) ? ld_once2(px2 + (tb + 3) * 1024) : z2;

        QSTEP(q0); QSTEP(q1); QSTEP(q2); QSTEP(q3);

        q0 = n0; q1 = n1; q2 = n2; q3 = n3;
    }
#undef QSTEP

    // final membrane potential: out[B*T*F + b*F + f]
    st_stream1(reinterpret_cast<u64*>(out + (size_t)Bn * Tn * Fn + (size_t)b * Fn) + fp,
               mem);
}

extern "C" void kernel_launch(void* const* d_in, const int* in_sizes, int n_in,
                              void* d_out, int out_size)
{
    (void)in_sizes; (void)n_in; (void)out_size;
    const float* x    = (const float*)d_in[0];
    const float* thr0 = (const float*)d_in[1];
    const float* cw   = (const float*)d_in[2];
    const float* cbp  = (const float*)d_in[3];
    const float* sa   = (const float*)d_in[4];
    float* out = (float*)d_out;

    lif_kernel<<<(Bn * Fn) / (BD * 2), BD>>>(x, thr0, cw, cbp, sa, out);
}

// round 14
// speedup vs baseline: 1.3525x; 1.0004x over previous
#include <cuda_runtime.h>

// EnhancedLIFNeuron on GB300: Conv1d(1,1,5,'same') + spatial attention + LIF scan.
// B=128, T=128, F=2048. Each thread owns ONE packed f32x2 pair (2 adjacent
// feature chains). No SMEM. Phase 1 streams x (evict_normal, stays in L2);
// phase 2 re-reads with ld.global.cs through a 4-deep register ring; stores
// st.global.cs. 7 blocks/SM (<=72 regs) -> all 1024 blocks in ONE wave.
// atan via min(|z|,1/|z|) range reduction: 1 MUFU rcp per lane per step.

#define Tn 128
#define Fn 2048
#define Bn 128
#define BD 128

typedef unsigned long long u64;

__device__ __forceinline__ u64 pk(float lo, float hi) {
    u64 r; asm("mov.b64 %0,{%1,%2};" : "=l"(r) : "f"(lo), "f"(hi)); return r;
}
__device__ __forceinline__ void upk(u64 v, float& lo, float& hi) {
    asm("mov.b64 {%0,%1},%2;" : "=f"(lo), "=f"(hi) : "l"(v));
}
__device__ __forceinline__ u64 f2fma(u64 a, u64 b, u64 c) {
    u64 d; asm("fma.rn.f32x2 %0,%1,%2,%3;" : "=l"(d) : "l"(a), "l"(b), "l"(c)); return d;
}
__device__ __forceinline__ u64 f2mul(u64 a, u64 b) {
    u64 d; asm("mul.rn.f32x2 %0,%1,%2;" : "=l"(d) : "l"(a), "l"(b)); return d;
}
__device__ __forceinline__ u64 f2add(u64 a, u64 b) {
    u64 d; asm("add.rn.f32x2 %0,%1,%2;" : "=l"(d) : "l"(a), "l"(b)); return d;
}
__device__ __forceinline__ float frcp_ap(float a) {
    float r; asm("rcp.approx.ftz.f32 %0,%1;" : "=f"(r) : "f"(a)); return r;
}
// phase-2 load: streaming (evict-first)
__device__ __forceinline__ float2 ld_once2(const float2* p) {
    float2 v;
    asm("ld.global.cs.v2.f32 {%0,%1},[%2];" : "=f"(v.x), "=f"(v.y) : "l"(p));
    return v;
}
// streaming store (evict-first)
__device__ __forceinline__ void st_stream1(u64* p, u64 a) {
    asm volatile("st.global.cs.b64 [%0],%1;" :: "l"(p), "l"(a) : "memory");
}

#define SMASK 0x8000000080000000ull

__global__ __launch_bounds__(BD, 7)
void lif_kernel(const float* __restrict__ x,
                const float* __restrict__ thr0p,
                const float* __restrict__ convw,
                const float* __restrict__ convb,
                const float* __restrict__ sap,
                float* __restrict__ out)
{
    const int cid = blockIdx.x * BD + threadIdx.x;    // pair-chain id
    const int b   = cid >> 10;                        // Fn/2 = 1024 pairs per batch
    const int fp  = cid & 1023;                       // pair index; f = 2*fp
    const float2* __restrict__ px2 =
        reinterpret_cast<const float2*>(x + (size_t)b * Tn * Fn) + fp;  // + t*1024

    // ---- scalars ----
    const float thr0 = __ldg(thr0p);
    const float w0 = __ldg(convw + 0), w1 = __ldg(convw + 1), w2 = __ldg(convw + 2),
                w3 = __ldg(convw + 3), w4 = __ldg(convw + 4);
    const float cb = __ldg(convb);
    const float sa = __ldg(sap);

    // ---- phase 1: packed sum over t (default loads keep x in L2) ----
    u64 a0 = 0, a1 = 0, a2 = 0, a3 = 0;
    float2 r0v, r1v, r2v, r126, r127;
    #pragma unroll 4
    for (int t = 0; t < Tn; t += 4) {
        float2 v0 = __ldg(px2 + (t + 0) * 1024);
        float2 v1 = __ldg(px2 + (t + 1) * 1024);
        float2 v2 = __ldg(px2 + (t + 2) * 1024);
        float2 v3 = __ldg(px2 + (t + 3) * 1024);
        if (t == 0)   { r0v = v0; r1v = v1; r2v = v2; }
        if (t == 124) { r126 = v2; r127 = v3; }
        a0 = f2add(a0, pk(v0.x, v0.y));
        a1 = f2add(a1, pk(v1.x, v1.y));
        a2 = f2add(a2, pk(v2.x, v2.y));
        a3 = f2add(a3, pk(v3.x, v3.y));
    }
    float s0, s1;
    upk(f2add(f2add(a0, a1), f2add(a2, a3)), s0, s1);

    // closed-form mean of conv output, then attention scale per lane
    const float W   = ((w0 + w1) + w2) + (w3 + w4);
    const float c34 = w3 + w4, c01 = w0 + w1;
#define MEANL(S, X0, X1, X126, X127) \
    ((W * (S) - c34 * (X0) - w4 * (X1) - w0 * (X126) - c01 * (X127)) * (1.0f/Tn) + cb)
    float m0 = MEANL(s0, r0v.x, r1v.x, r126.x, r127.x);
    float m1 = MEANL(s1, r0v.y, r1v.y, r126.y, r127.y);
#undef MEANL
    float sc0 = 1.0f + 0.5f / (1.0f + __expf(-sa * m0));   // GAMMA = 0.5
    float sc1 = 1.0f + 0.5f / (1.0f + __expf(-sa * m1));

    // scaled conv weights, packed
    const u64 V0 = pk(w0*sc0, w0*sc1);
    const u64 V1 = pk(w1*sc0, w1*sc1);
    const u64 V2 = pk(w2*sc0, w2*sc1);
    const u64 V3 = pk(w3*sc0, w3*sc1);
    const u64 V4 = pk(w4*sc0, w4*sc1);
    const u64 Vb = pk(cb*sc0, cb*sc1);

    // ---- packed constants ----
    const float PI = 3.14159265358979323846f;
    const float I2P = 0.5f / PI;                      // 1/(2*pi), folded into poly
    const u64 DEC  = pk(0.9f, 0.9f);                  // DECAY == ALPHA
    const u64 CARG = pk(PI*0.5f, PI*0.5f);
    const u64 QRT  = pk(0.25f, 0.25f);
    const u64 CAVG = pk(0.1f/3.0f, 0.1f/3.0f);
    const u64 CT0  = pk(0.1f*thr0, 0.1f*thr0);
    // atan(a)/(2pi) ~ a*(C0 + C1 a^2 + ... + C5 a^10), a in [0,1], deg-11 minimax
    const u64 C0 = pk( 0.99997726f*I2P,  0.99997726f*I2P);
    const u64 C1 = pk(-0.33262347f*I2P, -0.33262347f*I2P);
    const u64 C2 = pk( 0.19354346f*I2P,  0.19354346f*I2P);
    const u64 C3 = pk(-0.11643287f*I2P, -0.11643287f*I2P);
    const u64 C4 = pk( 0.05265332f*I2P,  0.05265332f*I2P);
    const u64 C5 = pk(-0.01172120f*I2P, -0.01172120f*I2P);

    // ---- LIF state, one packed pair ----
    u64 mem = 0, thr = pk(thr0, thr0), h2 = 0, h12 = 0;
    u64 xm2 = 0, xm1 = 0;
    u64 xc  = pk(r0v.x, r0v.y);
    u64 xp1 = pk(r1v.x, r1v.y);
    u64 xp2 = pk(r2v.x, r2v.y);

    // 4-deep prefetch ring: q = x[3..6]
    float2 q0 = ld_once2(px2 + 3*1024);
    float2 q1 = ld_once2(px2 + 4*1024);
    float2 q2 = ld_once2(px2 + 5*1024);
    float2 q3 = ld_once2(px2 + 6*1024);
    const float2 z2 = make_float2(0.f, 0.f);

    u64* __restrict__ opp =
        reinterpret_cast<u64*>(out + (size_t)b * Tn * Fn) + fp;  // + t*1024

#define QSTEP(Q) do {                                                        \
        u64 cv = f2fma(V0, xm2, f2fma(V1, xm1, f2fma(V2, xc,                 \
                 f2fma(V3, xp1, f2fma(V4, xp2, Vb)))));                      \
        mem = f2fma(DEC, mem, cv);                                           \
        u64 z  = f2mul(f2add(mem, thr ^ SMASK), CARG);                       \
        float zlo, zhi; upk(z, zlo, zhi);                                    \
        float azlo = fabsf(zlo), azhi = fabsf(zhi);                          \
        float alo = fminf(azlo, fabsf(frcp_ap(zlo)));                        \
        float ahi = fminf(azhi, fabsf(frcp_ap(zhi)));                        \
        u64 a  = pk(alo, ahi);                                               \
        u64 u  = f2mul(a, a);                                                \
        u64 u2 = f2mul(u, u);                                                \
        u64 pa = f2fma(C1, u, C0);                                           \
        u64 pb = f2fma(C3, u, C2);                                           \
        u64 pc = f2fma(C5, u, C4);                                           \
        u64 p  = f2fma(f2fma(pc, u2, pb), u2, pa);                           \
        u64 r  = f2mul(a, p);            /* atan(a)/(2pi) >= 0 */            \
        u64 sg = z & SMASK;                                                  \
        u64 sr = r ^ sg;                 /* sign(z)*r */                     \
        u64 eb = f2add(QRT ^ sg, sr ^ SMASK);  /* sign*0.25 - sign*r */      \
        float srlo, srhi; upk(sr, srlo, srhi);                               \
        float eblo, ebhi; upk(eb, eblo, ebhi);                               \
        float elo = (azlo > 1.0f) ? eblo : srlo;                             \
        float ehi = (azhi > 1.0f) ? ebhi : srhi;                             \
        u64 spike = f2add(QRT, pk(elo, ehi));                                \
        u64 s3 = f2add(h12, spike);                                          \
        thr = f2fma(DEC, thr, f2fma(CAVG, s3, CT0));                         \
        mem = f2fma(spike ^ SMASK, thr, mem);                                \
        h12 = f2add(h2, spike); h2 = spike;                                  \
        xm2 = xm1; xm1 = xc; xc = xp1; xp1 = xp2; xp2 = pk((Q).x, (Q).y);    \
        st_stream1(opp, spike); opp += 1024;                                 \
    } while (0)

    for (int g = 0; g < Tn; g += 4) {
        int tb = g + 7;   // prefetch 4-7 steps ahead
        float2 n0 = (tb + 0 < Tn) ? ld_once2(px2 + (tb + 0) * 1024) : z2;
        float2 n1 = (tb + 1 < Tn) ? ld_once2(px2 + (tb + 1) * 1024) : z2;
        float2 n2 = (tb + 2 < Tn) ? ld_once2(px2 + (tb + 2) * 1024) : z2;
        float2 n3 = (tb + 3 < Tn) ? ld_once2(px2 + (tb + 3) * 1024) : z2;

        QSTEP(q0); QSTEP(q1); QSTEP(q2); QSTEP(q3);

        q0 = n0; q1 = n1; q2 = n2; q3 = n3;
    }
#undef QSTEP

    // final membrane potential: out[B*T*F + b*F + f]
    st_stream1(reinterpret_cast<u64*>(out + (size_t)Bn * Tn * Fn + (size_t)b * Fn) + fp,
               mem);
}

extern "C" void kernel_launch(void* const* d_in, const int* in_sizes, int n_in,
                              void* d_out, int out_size)
{
    (void)in_sizes; (void)n_in; (void)out_size;
    const float* x    = (const float*)d_in[0];
    const float* thr0 = (const float*)d_in[1];
    const float* cw   = (const float*)d_in[2];
    const float* cbp  = (const float*)d_in[3];
    const float* sa   = (const float*)d_in[4];
    float* out = (float*)d_out;

    lif_kernel<<<(Bn * Fn) / (BD * 2), BD>>>(x, thr0, cw, cbp, sa, out);
}

// round 15
// speedup vs baseline: 1.3880x; 1.0263x over previous
#include <cuda_runtime.h>

// EnhancedLIFNeuron on GB300: Conv1d(1,1,5,'same') + spatial attention + LIF scan.
// B=128, T=128, F=2048. Each thread owns FOUR adjacent feature chains as TWO
// packed f32x2 streams (R8 structure, best so far). Phase 1 = high-MLP batched
// streaming sum (8 float4 loads in flight per iter, x stays in L2 evict_normal);
// phase 2 re-reads via ld.global.cs through a 4-deep register ring; stores
// st.global.cs. grid=512, block=128, 4 blocks/SM.

#define Tn 128
#define Fn 2048
#define Bn 128

typedef unsigned long long u64;

__device__ __forceinline__ u64 pk(float lo, float hi) {
    u64 r; asm("mov.b64 %0,{%1,%2};" : "=l"(r) : "f"(lo), "f"(hi)); return r;
}
__device__ __forceinline__ void upk(u64 v, float& lo, float& hi) {
    asm("mov.b64 {%0,%1},%2;" : "=f"(lo), "=f"(hi) : "l"(v));
}
__device__ __forceinline__ u64 f2fma(u64 a, u64 b, u64 c) {
    u64 d; asm("fma.rn.f32x2 %0,%1,%2,%3;" : "=l"(d) : "l"(a), "l"(b), "l"(c)); return d;
}
__device__ __forceinline__ u64 f2mul(u64 a, u64 b) {
    u64 d; asm("mul.rn.f32x2 %0,%1,%2;" : "=l"(d) : "l"(a), "l"(b)); return d;
}
__device__ __forceinline__ u64 f2add(u64 a, u64 b) {
    u64 d; asm("add.rn.f32x2 %0,%1,%2;" : "=l"(d) : "l"(a), "l"(b)); return d;
}
__device__ __forceinline__ float frcp_ap(float a) {
    float r; asm("rcp.approx.ftz.f32 %0,%1;" : "=f"(r) : "f"(a)); return r;
}
__device__ __forceinline__ float fsqrt_ap(float a) {
    float r; asm("sqrt.approx.ftz.f32 %0,%1;" : "=f"(r) : "f"(a)); return r;
}
// phase-2 load: streaming (evict-first)
__device__ __forceinline__ float4 ld_once4(const float4* p) {
    float4 v;
    asm("ld.global.cs.v4.f32 {%0,%1,%2,%3},[%4];"
        : "=f"(v.x), "=f"(v.y), "=f"(v.z), "=f"(v.w) : "l"(p));
    return v;
}
// streaming store (evict-first)
__device__ __forceinline__ void st_stream2(ulonglong2* p, u64 a, u64 b) {
    asm volatile("st.global.cs.v2.u64 [%0],{%1,%2};" :: "l"(p), "l"(a), "l"(b) : "memory");
}

#define SMASK 0x8000000080000000ull

__global__ __launch_bounds__(128, 4)
void lif_kernel(const float* __restrict__ x,
                const float* __restrict__ thr0p,
                const float* __restrict__ convw,
                const float* __restrict__ convb,
                const float* __restrict__ sap,
                float* __restrict__ out)
{
    const int cid = blockIdx.x * 128 + threadIdx.x;   // quad-chain id
    const int b   = cid >> 9;                         // Fn/4 = 512 quads per batch
    const int fq  = cid & 511;
    const float4* __restrict__ px4 =
        reinterpret_cast<const float4*>(x + (size_t)b * Tn * Fn) + fq;  // + t*512

    // ---- scalars ----
    const float thr0 = __ldg(thr0p);
    const float w0 = __ldg(convw + 0), w1 = __ldg(convw + 1), w2 = __ldg(convw + 2),
                w3 = __ldg(convw + 3), w4 = __ldg(convw + 4);
    const float cb = __ldg(convb);
    const float sa = __ldg(sap);

    // ---- phase 1: packed sums over t, 8 loads in flight per iter ----
    u64 aA0 = 0, aA1 = 0, aB0 = 0, aB1 = 0;
    #pragma unroll 2
    for (int t = 0; t < Tn; t += 8) {
        float4 v0 = __ldg(px4 + (t + 0) * 512);
        float4 v1 = __ldg(px4 + (t + 1) * 512);
        float4 v2 = __ldg(px4 + (t + 2) * 512);
        float4 v3 = __ldg(px4 + (t + 3) * 512);
        float4 v4 = __ldg(px4 + (t + 4) * 512);
        float4 v5 = __ldg(px4 + (t + 5) * 512);
        float4 v6 = __ldg(px4 + (t + 6) * 512);
        float4 v7 = __ldg(px4 + (t + 7) * 512);
        aA0 = f2add(aA0, f2add(pk(v0.x, v0.y), pk(v4.x, v4.y)));
        aB0 = f2add(aB0, f2add(pk(v0.z, v0.w), pk(v4.z, v4.w)));
        aA1 = f2add(aA1, f2add(pk(v1.x, v1.y), pk(v5.x, v5.y)));
        aB1 = f2add(aB1, f2add(pk(v1.z, v1.w), pk(v5.z, v5.w)));
        aA0 = f2add(aA0, f2add(pk(v2.x, v2.y), pk(v6.x, v6.y)));
        aB0 = f2add(aB0, f2add(pk(v2.z, v2.w), pk(v6.z, v6.w)));
        aA1 = f2add(aA1, f2add(pk(v3.x, v3.y), pk(v7.x, v7.y)));
        aB1 = f2add(aB1, f2add(pk(v3.z, v3.w), pk(v7.z, v7.w)));
    }
    float sA0, sA1, sB0, sB1;
    upk(f2add(aA0, aA1), sA0, sA1);
    upk(f2add(aB0, aB1), sB0, sB1);

    // boundary rows (L1/L2 hot after phase 1)
    float4 r0   = __ldg(px4 + 0 * 512);
    float4 r1   = __ldg(px4 + 1 * 512);
    float4 r2   = __ldg(px4 + 2 * 512);
    float4 r126 = __ldg(px4 + 126 * 512);
    float4 r127 = __ldg(px4 + 127 * 512);

    // closed-form mean of conv output, then attention scale per lane
    const float W   = ((w0 + w1) + w2) + (w3 + w4);
    const float c34 = w3 + w4, c01 = w0 + w1;
#define MEANL(S, X0, X1, X126, X127) \
    ((W * (S) - c34 * (X0) - w4 * (X1) - w0 * (X126) - c01 * (X127)) * (1.0f/Tn) + cb)
    float m0 = MEANL(sA0, r0.x, r1.x, r126.x, r127.x);
    float m1 = MEANL(sA1, r0.y, r1.y, r126.y, r127.y);
    float m2 = MEANL(sB0, r0.z, r1.z, r126.z, r127.z);
    float m3 = MEANL(sB1, r0.w, r1.w, r126.w, r127.w);
#undef MEANL
    float sc0 = 1.0f + 0.5f / (1.0f + __expf(-sa * m0));   // GAMMA = 0.5
    float sc1 = 1.0f + 0.5f / (1.0f + __expf(-sa * m1));
    float sc2 = 1.0f + 0.5f / (1.0f + __expf(-sa * m2));
    float sc3 = 1.0f + 0.5f / (1.0f + __expf(-sa * m3));

    // scaled conv weights, packed per pair
    const u64 VA0 = pk(w0*sc0, w0*sc1), VB0 = pk(w0*sc2, w0*sc3);
    const u64 VA1 = pk(w1*sc0, w1*sc1), VB1 = pk(w1*sc2, w1*sc3);
    const u64 VA2 = pk(w2*sc0, w2*sc1), VB2 = pk(w2*sc2, w2*sc3);
    const u64 VA3 = pk(w3*sc0, w3*sc1), VB3 = pk(w3*sc2, w3*sc3);
    const u64 VA4 = pk(w4*sc0, w4*sc1), VB4 = pk(w4*sc2, w4*sc3);
    const u64 VAb = pk(cb*sc0, cb*sc1), VBb = pk(cb*sc2, cb*sc3);

    // ---- packed constants ----
    const float PI = 3.14159265358979323846f;
    const float INVPI = 1.0f / PI;
    const u64 DEC  = pk(0.9f, 0.9f);                  // DECAY == ALPHA
    const u64 CARG = pk(PI*0.5f, PI*0.5f);
    const u64 QRT  = pk(0.25f, 0.25f);
    const u64 ONE  = pk(1.0f, 1.0f);
    const u64 CAVG = pk(0.1f/3.0f, 0.1f/3.0f);
    const u64 CT0  = pk(0.1f*thr0, 0.1f*thr0);
    const u64 P0 = pk( 0.9998660f*INVPI,  0.9998660f*INVPI);
    const u64 P1 = pk(-0.3302995f*INVPI, -0.3302995f*INVPI);
    const u64 P2 = pk( 0.1801410f*INVPI,  0.1801410f*INVPI);
    const u64 P3 = pk(-0.0851330f*INVPI, -0.0851330f*INVPI);
    const u64 P4 = pk( 0.0208351f*INVPI,  0.0208351f*INVPI);

    // ---- LIF state, two packed pairs (A = f,f+1 ; B = f+2,f+3) ----
    u64 memA = 0, thrA = pk(thr0, thr0), h2A = 0, h12A = 0;
    u64 memB = 0, thrB = pk(thr0, thr0), h2B = 0, h12B = 0;
    u64 am2 = 0, am1 = 0, ac = pk(r0.x, r0.y), ap1 = pk(r1.x, r1.y), ap2 = pk(r2.x, r2.y);
    u64 bm2 = 0, bm1 = 0, bc = pk(r0.z, r0.w), bp1 = pk(r1.z, r1.w), bp2 = pk(r2.z, r2.w);

    float4 q0 = ld_once4(px4 + 3*512);
    float4 q1 = ld_once4(px4 + 4*512);
    float4 q2 = ld_once4(px4 + 5*512);
    float4 q3 = ld_once4(px4 + 6*512);
    const float4 z4 = make_float4(0.f, 0.f, 0.f, 0.f);

    ulonglong2* __restrict__ opp =
        reinterpret_cast<ulonglong2*>(out + (size_t)b * Tn * Fn) + fq;  // + t*512

#define PAIRSTEP(mem, thr, h2, h12, xm2, xm1, xc, xp1, xp2, V0,V1,V2,V3,V4,Vb, XNEW, SPK) \
    do {                                                                     \
        u64 cv = f2fma(V0, xm2, f2fma(V1, xm1, f2fma(V2, xc,                 \
                 f2fma(V3, xp1, f2fma(V4, xp2, Vb)))));                      \
        mem = f2fma(DEC, mem, cv);                                           \
        u64 z  = f2mul(f2add(mem, thr ^ SMASK), CARG);                       \
        u64 o  = f2fma(z, z, ONE);                                           \
        float olo, ohi; upk(o, olo, ohi);                                    \
        float rlo = frcp_ap(1.0f + fsqrt_ap(olo));                           \
        float rhi = frcp_ap(1.0f + fsqrt_ap(ohi));                           \
        u64 tq = f2mul(z, pk(rlo, rhi));                                     \
        u64 tt = f2mul(tq, tq);                                              \
        u64 p  = f2fma(f2fma(f2fma(f2fma(P4, tt, P3), tt, P2), tt, P1), tt, P0); \
        u64 spike = f2fma(tq, p, QRT);                                       \
        u64 s3 = f2add(h12, spike);                                          \
        thr = f2fma(DEC, thr, f2fma(CAVG, s3, CT0));                         \
        mem = f2fma(spike ^ SMASK, thr, mem);                                \
        h12 = f2add(h2, spike); h2 = spike;                                  \
        xm2 = xm1; xm1 = xc; xc = xp1; xp1 = xp2; xp2 = (XNEW);              \
        SPK = spike;                                                         \
    } while (0)

#define QSTEP(Q) do {                                                        \
        u64 spA, spB;                                                        \
        PAIRSTEP(memA, thrA, h2A, h12A, am2, am1, ac, ap1, ap2,              \
                 VA0,VA1,VA2,VA3,VA4,VAb, pk((Q).x,(Q).y), spA);             \
        PAIRSTEP(memB, thrB, h2B, h12B, bm2, bm1, bc, bp1, bp2,              \
                 VB0,VB1,VB2,VB3,VB4,VBb, pk((Q).z,(Q).w), spB);             \
        st_stream2(opp, spA, spB); opp += 512;                               \
    } while (0)

    for (int g = 0; g < Tn; g += 4) {
        int tb = g + 7;   // prefetch 4-7 steps ahead
        float4 n0 = (tb + 0 < Tn) ? ld_once4(px4 + (tb + 0) * 512) : z4;
        float4 n1 = (tb + 1 < Tn) ? ld_once4(px4 + (tb + 1) * 512) : z4;
        float4 n2 = (tb + 2 < Tn) ? ld_once4(px4 + (tb + 2) * 512) : z4;
        float4 n3 = (tb + 3 < Tn) ? ld_once4(px4 + (tb + 3) * 512) : z4;

        QSTEP(q0); QSTEP(q1); QSTEP(q2); QSTEP(q3);

        q0 = n0; q1 = n1; q2 = n2; q3 = n3;
    }
#undef QSTEP
#undef PAIRSTEP

    // final membrane potential: out[B*T*F + b*F + f]
    st_stream2(reinterpret_cast<ulonglong2*>(out + (size_t)Bn * Tn * Fn + (size_t)b * Fn) + fq,
               memA, memB);
}

extern "C" void kernel_launch(void* const* d_in, const int* in_sizes, int n_in,
                              void* d_out, int out_size)
{
    (void)in_sizes; (void)n_in; (void)out_size;
    const float* x    = (const float*)d_in[0];
    const float* thr0 = (const float*)d_in[1];
    const float* cw   = (const float*)d_in[2];
    const float* cbp  = (const float*)d_in[3];
    const float* sa   = (const float*)d_in[4];
    float* out = (float*)d_out;

    lif_kernel<<<(Bn * Fn) / (128 * 4), 128>>>(x, thr0, cw, cbp, sa, out);
}